// round 16
// baseline (speedup 1.0000x reference)
#include <cuda_runtime.h>

// FeedForwardQuantum: out = relu(cos(x+theta) @ W1 + b1) @ W2 + b2
// x: [524288, 8] fp32, W1: [8,32], W2: [32,8].
// R7: RPT=4 (best proven skeleton, R2=15.84us kernel) with:
//  - no __constant__/no memcpy node: prep packs weights into __device__ global,
//    main kernel reads via __ldg float4 (L1-hot, uniform; LDG floor 4 < LDC 8)
//  - __cosf direct (|x+theta| small; MUFU err ~1e-6 << 1e-3 gate)
//  - 2.65us of graph-node overhead (memcpy) deleted

#define EDIM 8
#define FDIM 32
#define RPT 4      // rows per thread (two f32x2 pairs)
#define BLOCK 128

struct GW {
    float4 wf[FDIM * 4];  // per f: [w1col e0-3][w1col e4-7][w2row e0-3][w2row e4-7]
    float  b1[FDIM];
    float  b2[EDIM];
};

__device__ GW g_w;   // packed by prep kernel; L1-resident in main kernel

// packed f32x2 ops (float2 carriage; ptxas coalesces the pack movs)
__device__ __forceinline__ float2 ffma2(float2 a, float2 b, float2 c) {
    float2 d;
    asm("{\n\t"
        ".reg .b64 ra, rb, rc, rd;\n\t"
        "mov.b64 ra, {%2, %3};\n\t"
        "mov.b64 rb, {%4, %5};\n\t"
        "mov.b64 rc, {%6, %7};\n\t"
        "fma.rn.f32x2 rd, ra, rb, rc;\n\t"
        "mov.b64 {%0, %1}, rd;\n\t"
        "}"
        : "=f"(d.x), "=f"(d.y)
        : "f"(a.x), "f"(a.y), "f"(b.x), "f"(b.y), "f"(c.x), "f"(c.y));
    return d;
}
__device__ __forceinline__ float2 dup2(float v) { return make_float2(v, v); }

__global__ void ffq_prep(const float* __restrict__ w1, const float* __restrict__ b1,
                         const float* __restrict__ w2, const float* __restrict__ b2)
{
    int f = threadIdx.x;
    if (f < FDIM) {
        g_w.wf[f * 4 + 0] = make_float4(w1[0 * FDIM + f], w1[1 * FDIM + f],
                                        w1[2 * FDIM + f], w1[3 * FDIM + f]);
        g_w.wf[f * 4 + 1] = make_float4(w1[4 * FDIM + f], w1[5 * FDIM + f],
                                        w1[6 * FDIM + f], w1[7 * FDIM + f]);
        const float4* w2v = reinterpret_cast<const float4*>(w2);
        g_w.wf[f * 4 + 2] = w2v[f * 2 + 0];
        g_w.wf[f * 4 + 3] = w2v[f * 2 + 1];
        g_w.b1[f] = b1[f];
        if (f < EDIM) g_w.b2[f] = b2[f];
    }
}

__global__ void __launch_bounds__(BLOCK)
ffq_kernel(const float* __restrict__ x, const float* __restrict__ theta,
           float* __restrict__ out, long long nrows)
{
    const int t = threadIdx.x;
    const long long idx  = (long long)blockIdx.x * BLOCK + t;
    const long long row0 = idx * RPT;
    if (row0 >= nrows) return;

    float th[EDIM];
#pragma unroll
    for (int e = 0; e < EDIM; e++) th[e] = __ldg(theta + e);

    const float4* __restrict__ wfp = &g_w.wf[0];

    if (row0 + RPT <= nrows) {
        // ---- fast path: 4 rows; q packed as (row_i, row_j) f32x2 pairs ----
        const float4* xp = reinterpret_cast<const float4*>(x + row0 * EDIM);
        float2 q01[EDIM], q23[EDIM];
        {
            float4 a0 = xp[0], a1 = xp[1];   // row 0
            float4 b0 = xp[2], b1v = xp[3];  // row 1
            q01[0] = make_float2(__cosf(a0.x + th[0]), __cosf(b0.x + th[0]));
            q01[1] = make_float2(__cosf(a0.y + th[1]), __cosf(b0.y + th[1]));
            q01[2] = make_float2(__cosf(a0.z + th[2]), __cosf(b0.z + th[2]));
            q01[3] = make_float2(__cosf(a0.w + th[3]), __cosf(b0.w + th[3]));
            q01[4] = make_float2(__cosf(a1.x + th[4]), __cosf(b1v.x + th[4]));
            q01[5] = make_float2(__cosf(a1.y + th[5]), __cosf(b1v.y + th[5]));
            q01[6] = make_float2(__cosf(a1.z + th[6]), __cosf(b1v.z + th[6]));
            q01[7] = make_float2(__cosf(a1.w + th[7]), __cosf(b1v.w + th[7]));
        }
        {
            float4 a0 = xp[4], a1 = xp[5];   // row 2
            float4 b0 = xp[6], b1v = xp[7];  // row 3
            q23[0] = make_float2(__cosf(a0.x + th[0]), __cosf(b0.x + th[0]));
            q23[1] = make_float2(__cosf(a0.y + th[1]), __cosf(b0.y + th[1]));
            q23[2] = make_float2(__cosf(a0.z + th[2]), __cosf(b0.z + th[2]));
            q23[3] = make_float2(__cosf(a0.w + th[3]), __cosf(b0.w + th[3]));
            q23[4] = make_float2(__cosf(a1.x + th[4]), __cosf(b1v.x + th[4]));
            q23[5] = make_float2(__cosf(a1.y + th[5]), __cosf(b1v.y + th[5]));
            q23[6] = make_float2(__cosf(a1.z + th[6]), __cosf(b1v.z + th[6]));
            q23[7] = make_float2(__cosf(a1.w + th[7]), __cosf(b1v.w + th[7]));
        }

        float2 acc01[EDIM], acc23[EDIM];
#pragma unroll
        for (int e = 0; e < EDIM; e++) {
            float b = __ldg(&g_w.b2[e]);
            acc01[e] = dup2(b);
            acc23[e] = dup2(b);
        }

#pragma unroll
        for (int f = 0; f < FDIM; f++) {
            float4 wa = __ldg(wfp + f * 4 + 0);   // w1[e0..3][f]
            float4 wb = __ldg(wfp + f * 4 + 1);   // w1[e4..7][f]
            float  bf = __ldg(&g_w.b1[f]);
            float2 bfp = dup2(bf);

            float2 h01 = ffma2(q01[0], dup2(wa.x), bfp);
            float2 h23 = ffma2(q23[0], dup2(wa.x), bfp);
            h01 = ffma2(q01[1], dup2(wa.y), h01);  h23 = ffma2(q23[1], dup2(wa.y), h23);
            h01 = ffma2(q01[2], dup2(wa.z), h01);  h23 = ffma2(q23[2], dup2(wa.z), h23);
            h01 = ffma2(q01[3], dup2(wa.w), h01);  h23 = ffma2(q23[3], dup2(wa.w), h23);
            h01 = ffma2(q01[4], dup2(wb.x), h01);  h23 = ffma2(q23[4], dup2(wb.x), h23);
            h01 = ffma2(q01[5], dup2(wb.y), h01);  h23 = ffma2(q23[5], dup2(wb.y), h23);
            h01 = ffma2(q01[6], dup2(wb.z), h01);  h23 = ffma2(q23[6], dup2(wb.z), h23);
            h01 = ffma2(q01[7], dup2(wb.w), h01);  h23 = ffma2(q23[7], dup2(wb.w), h23);

            h01.x = fmaxf(h01.x, 0.0f); h01.y = fmaxf(h01.y, 0.0f);
            h23.x = fmaxf(h23.x, 0.0f); h23.y = fmaxf(h23.y, 0.0f);

            float4 va = __ldg(wfp + f * 4 + 2);   // w2[f][e0..3]
            float4 vb = __ldg(wfp + f * 4 + 3);   // w2[f][e4..7]
            float2 wp;
            wp = dup2(va.x); acc01[0] = ffma2(h01, wp, acc01[0]); acc23[0] = ffma2(h23, wp, acc23[0]);
            wp = dup2(va.y); acc01[1] = ffma2(h01, wp, acc01[1]); acc23[1] = ffma2(h23, wp, acc23[1]);
            wp = dup2(va.z); acc01[2] = ffma2(h01, wp, acc01[2]); acc23[2] = ffma2(h23, wp, acc23[2]);
            wp = dup2(va.w); acc01[3] = ffma2(h01, wp, acc01[3]); acc23[3] = ffma2(h23, wp, acc23[3]);
            wp = dup2(vb.x); acc01[4] = ffma2(h01, wp, acc01[4]); acc23[4] = ffma2(h23, wp, acc23[4]);
            wp = dup2(vb.y); acc01[5] = ffma2(h01, wp, acc01[5]); acc23[5] = ffma2(h23, wp, acc23[5]);
            wp = dup2(vb.z); acc01[6] = ffma2(h01, wp, acc01[6]); acc23[6] = ffma2(h23, wp, acc23[6]);
            wp = dup2(vb.w); acc01[7] = ffma2(h01, wp, acc01[7]); acc23[7] = ffma2(h23, wp, acc23[7]);
        }

        float4* op = reinterpret_cast<float4*>(out + row0 * EDIM);
        op[0] = make_float4(acc01[0].x, acc01[1].x, acc01[2].x, acc01[3].x);
        op[1] = make_float4(acc01[4].x, acc01[5].x, acc01[6].x, acc01[7].x);
        op[2] = make_float4(acc01[0].y, acc01[1].y, acc01[2].y, acc01[3].y);
        op[3] = make_float4(acc01[4].y, acc01[5].y, acc01[6].y, acc01[7].y);
        op[4] = make_float4(acc23[0].x, acc23[1].x, acc23[2].x, acc23[3].x);
        op[5] = make_float4(acc23[4].x, acc23[5].x, acc23[6].x, acc23[7].x);
        op[6] = make_float4(acc23[0].y, acc23[1].y, acc23[2].y, acc23[3].y);
        op[7] = make_float4(acc23[4].y, acc23[5].y, acc23[6].y, acc23[7].y);
    } else {
        // ---- tail: scalar per-row fallback ----
        for (long long r = row0; r < nrows; r++) {
            float q[EDIM];
#pragma unroll
            for (int e = 0; e < EDIM; e++) q[e] = __cosf(x[r * EDIM + e] + th[e]);
            float o[EDIM];
#pragma unroll
            for (int e = 0; e < EDIM; e++) o[e] = g_w.b2[e];
            for (int f = 0; f < FDIM; f++) {
                float h = g_w.b1[f];
                const float* w1c = reinterpret_cast<const float*>(&g_w.wf[f * 4 + 0]);
                const float* w2r = reinterpret_cast<const float*>(&g_w.wf[f * 4 + 2]);
#pragma unroll
                for (int e = 0; e < EDIM; e++) h = fmaf(q[e], w1c[e], h);
                h = fmaxf(h, 0.0f);
#pragma unroll
                for (int e = 0; e < EDIM; e++) o[e] = fmaf(h, w2r[e], o[e]);
            }
#pragma unroll
            for (int e = 0; e < EDIM; e++) out[r * EDIM + e] = o[e];
        }
    }
}

extern "C" void kernel_launch(void* const* d_in, const int* in_sizes, int n_in,
                              void* d_out, int out_size) {
    const float* x     = (const float*)d_in[0];
    const float* theta = (const float*)d_in[1];
    const float* w1    = (const float*)d_in[2];
    const float* b1    = (const float*)d_in[3];
    const float* w2    = (const float*)d_in[4];
    const float* b2    = (const float*)d_in[5];
    float* out = (float*)d_out;

    long long nrows = (long long)in_sizes[0] / EDIM;
    long long nthreads = (nrows + RPT - 1) / RPT;
    int blocks = (int)((nthreads + BLOCK - 1) / BLOCK);

    // pack weights into __device__ global (no constant, no memcpy node)
    ffq_prep<<<1, 64>>>(w1, b1, w2, b2);
    ffq_kernel<<<blocks, BLOCK>>>(x, theta, out, nrows);
}